// round 1
// baseline (speedup 1.0000x reference)
#include <cuda_runtime.h>
#include <cuda_bf16.h>
#include <math.h>

#define BB 8192
#define FF 24
#define VV 100000
#define DD 64
#define PP 276  // FF*(FF-1)/2

// Scratch (allocation-free rule: __device__ globals)
__device__ float g_wpair[PP * 2];  // interleaved: [wMul, wD] per pair
__device__ float g_cA[FF];         // per-field coefficient for the s_plus term

// ---------------------------------------------------------------------------
// Prep kernel: fold arch_w (and flag semantics) into {wMul, wD} per pair and
// cA per field.
//   t_p = wS*s_plus + wMul*s_mul + wD*s_absdiff
//   wS = w0 + w4 + 0.5*(w2+w3);  wMul = w1;  wD = 0.5*(w2-w3)
//   flag==0 == flag==1 with one-hot(argmax) weights.
//   cA[f] = sum over pairs containing f of wS_p  (s_plus decomposition)
// ---------------------------------------------------------------------------
__global__ void ofm_prep_kernel(const float* __restrict__ arch_w,
                                const int* __restrict__ flagp) {
    int t = threadIdx.x;
    if (t < FF) g_cA[t] = 0.0f;
    __syncthreads();
    if (t < PP) {
        // pair index -> (i, j), tril_indices(-1) row-major order
        int i = 1, p = t;
        while (p >= i) { p -= i; i++; }
        int j = p;

        float w[5];
#pragma unroll
        for (int k = 0; k < 5; k++) w[k] = arch_w[t * 5 + k];

        if (*flagp == 0) {
            // one-hot(argmax, first max wins)
            int sel = 0;
            float best = w[0];
#pragma unroll
            for (int k = 1; k < 5; k++) {
                if (w[k] > best) { best = w[k]; sel = k; }
            }
#pragma unroll
            for (int k = 0; k < 5; k++) w[k] = (k == sel) ? 1.0f : 0.0f;
        }

        float wS = w[0] + w[4] + 0.5f * (w[2] + w[3]);
        g_wpair[2 * t + 0] = w[1];                  // s_mul weight
        g_wpair[2 * t + 1] = 0.5f * (w[2] - w[3]);  // s_absdiff weight
        atomicAdd(&g_cA[i], wS);
        atomicAdd(&g_cA[j], wS);
    }
}

// ---------------------------------------------------------------------------
// Main kernel: one warp per batch row. Each lane owns 2 of the 64 dims
// (float2), keeping the 24x64 e2 tile in 48 registers. Fully unrolled
// 276-pair loop; pair weights broadcast from shared memory.
// ---------------------------------------------------------------------------
__global__ __launch_bounds__(256) void ofm_main_kernel(
    const int* __restrict__ x,
    const float* __restrict__ emb2,
    const float* __restrict__ emb1,
    const float* __restrict__ bias,
    float* __restrict__ out) {

    __shared__ float2 s_w[PP];
    __shared__ float s_cA[FF];

    int tid = threadIdx.x;
    for (int k = tid; k < PP; k += 256)
        s_w[k] = reinterpret_cast<const float2*>(g_wpair)[k];
    if (tid < FF) s_cA[tid] = g_cA[tid];
    __syncthreads();

    int warp = tid >> 5;
    int lane = tid & 31;
    int row = blockIdx.x * 8 + warp;  // BB % 8 == 0, grid = BB/8 -> no bounds check

    // Gather x indices + emb1 values (lanes 0..23)
    int xv = 0;
    float e1v = 0.0f;
    if (lane < FF) {
        xv = x[row * FF + lane];
        e1v = emb1[(size_t)lane * VV + xv];
    }

    // Gather e2 tile: 24 fields x float2 per lane (256B coalesced per field)
    float2 e[FF];
#pragma unroll
    for (int f = 0; f < FF; f++) {
        int xf = __shfl_sync(0xffffffffu, xv, f);
        const float2* ptr =
            reinterpret_cast<const float2*>(emb2 + ((size_t)f * VV + xf) * DD) + lane;
        e[f] = __ldg(ptr);
    }

    // out_first contribution (only lanes < FF carry an e1 value)
    float acc = (lane < FF) ? e1v : 0.0f;

    // s_plus term, decomposed per field
#pragma unroll
    for (int f = 0; f < FF; f++)
        acc = fmaf(s_cA[f], e[f].x + e[f].y, acc);

    // Pair loop: weighted dot + weighted abs-diff, fully unrolled
#pragma unroll
    for (int i = 1; i < FF; i++) {
#pragma unroll
        for (int j = 0; j < i; j++) {
            const int p = i * (i - 1) / 2 + j;
            float2 w = s_w[p];
            float dot = fmaf(e[i].y, e[j].y, e[i].x * e[j].x);
            float ad = fabsf(e[i].x - e[j].x) + fabsf(e[i].y - e[j].y);
            acc = fmaf(w.x, dot, fmaf(w.y, ad, acc));
        }
    }

    // Warp reduction over the 32 lanes (covers all 64 dims + e1 partials)
#pragma unroll
    for (int o = 16; o; o >>= 1)
        acc += __shfl_xor_sync(0xffffffffu, acc, o);

    if (lane == 0) {
        float z = acc + bias[0];
        out[row] = 1.0f / (1.0f + expf(-z));
    }
}

// ---------------------------------------------------------------------------
// d_in order (metadata): 0=x(int32 B*F), 1=flag(int32), 2=emb2(f32 F*V*D),
//                        3=emb1(f32 F*V), 4=bias(f32 1), 5=arch_w(f32 P*5)
// ---------------------------------------------------------------------------
extern "C" void kernel_launch(void* const* d_in, const int* in_sizes, int n_in,
                              void* d_out, int out_size) {
    const int* x = (const int*)d_in[0];
    const int* flag = (const int*)d_in[1];
    const float* emb2 = (const float*)d_in[2];
    const float* emb1 = (const float*)d_in[3];
    const float* bias = (const float*)d_in[4];
    const float* arch_w = (const float*)d_in[5];
    float* out = (float*)d_out;

    ofm_prep_kernel<<<1, 288>>>(arch_w, flag);
    ofm_main_kernel<<<BB / 8, 256>>>(x, emb2, emb1, bias, out);
}